// round 8
// baseline (speedup 1.0000x reference)
#include <cuda_runtime.h>
#include <cuda_bf16.h>

// Tree: BRANCH=8, DEPTH=4. Level sizes 1,8,64,512,4096; offsets 0,1,9,73,585,4681.
// parent(c) = (c-1)>>3 for all c >= 1.
#define E_TOTAL   4681
#define NT        512

__global__ __launch_bounds__(NT)
void softmax_cascade_kernel(const float* __restrict__ x,
                            float* __restrict__ out)
{
    const int row = blockIdx.x;
    const size_t base = (size_t)row * E_TOTAL;

    // buf holds the row shifted by s = base&3 elements so that
    // buf[s + e] has the SAME 16B phase as x[base + e] -> aligned float4 ops.
    __shared__ __align__(16) float buf[E_TOTAL + 4];
    __shared__ float rs[585];     // per-group softmax ratio of internal nodes

    const int t = threadIdx.x;
    const int s    = (int)(base & 3);
    const int head = (4 - s) & 3;                 // scalar elements at row start
    const int nvec = (E_TOTAL - head) >> 2;       // aligned float4 count
    const int tailstart = head + (nvec << 2);
    const int ntail = E_TOTAL - tailstart;        // 0..3 scalar at end

    // ---------------- copy-in: aligned float4 stream ----------------------
    {
        const float4* __restrict__ vsrc = (const float4*)(x + base + head);
        for (int i = t; i < nvec; i += NT)        // s+head+4i ∈ {4i, 4i+4}: aligned
            *(float4*)(buf + s + head + 4 * i) = vsrc[i];
        if (t < head)
            buf[s + t] = x[base + t];
        if (t >= 32 && t - 32 < ntail)
            buf[s + tailstart + (t - 32)] = x[base + tailstart + (t - 32)];
    }
    __syncthreads();

    // ------------- Phase A: per-group softmax ratios (all levels) ---------
    // Thread t handles node c = 1+t; 8-child groups are 8-aligned in t.
    {
        float e = __expf(buf[s + 1 + t]);
        float g = e;
        g += __shfl_xor_sync(0xffffffffu, g, 1);
        g += __shfl_xor_sync(0xffffffffu, g, 2);
        g += __shfl_xor_sync(0xffffffffu, g, 4);
        rs[1 + t] = __fdividef(e, g);
    }
    if (t < 128) {   // warps 0-3 fully active; t>=72 lanes compute garbage, discarded
        float e = __expf(buf[s + 513 + t]);
        float g = e;
        g += __shfl_xor_sync(0xffffffffu, g, 1);
        g += __shfl_xor_sync(0xffffffffu, g, 2);
        g += __shfl_xor_sync(0xffffffffu, g, 4);
        if (t < 72) rs[513 + t] = __fdividef(e, g);
    }
    __syncthreads();

    // ------------- Phase B: path products -> finals into buf --------------
    {
        const int c  = 73 + t;          // level-3 node
        const int p2 = (c - 1) >> 3;    // level-2 parent
        const int p1 = (p2 - 1) >> 3;   // level-1 ancestor
        buf[s + c] = rs[c] * rs[p2] * rs[p1];
    }
    if (t < 73) {
        if (t == 72) {
            buf[s] = 1.0f;              // root
        } else {
            const int c = 1 + t;        // levels 1..2
            float p = rs[c];
            if (c >= 9) p *= rs[(c - 1) >> 3];
            buf[s + c] = p;
        }
    }
    __syncthreads();

    // ------------- Leaves: in-place in smem -------------------------------
#pragma unroll
    for (int i = 0; i < 8; ++i) {
        const int idx = i * NT + t;     // 0..4095
        float e = __expf(buf[s + 585 + idx]);
        float g = e;
        g += __shfl_xor_sync(0xffffffffu, g, 1);
        g += __shfl_xor_sync(0xffffffffu, g, 2);
        g += __shfl_xor_sync(0xffffffffu, g, 4);
        buf[s + 585 + idx] = __fdividef(e, g) * buf[s + 73 + (idx >> 3)];
    }
    __syncthreads();

    // ---------------- copy-out: aligned float4 stream ---------------------
    {
        float4* __restrict__ vdst = (float4*)(out + base + head);
        for (int i = t; i < nvec; i += NT)
            vdst[i] = *(const float4*)(buf + s + head + 4 * i);
        if (t < head)
            out[base + t] = buf[s + t];
        if (t >= 32 && t - 32 < ntail)
            out[base + tailstart + (t - 32)] = buf[s + tailstart + (t - 32)];
    }
}

extern "C" void kernel_launch(void* const* d_in, const int* in_sizes, int n_in,
                              void* d_out, int out_size)
{
    const float* x = (const float*)d_in[0];   // inputs [B, E] fp32
    float* out = (float*)d_out;
    const int batch = in_sizes[0] / E_TOTAL;  // 8192
    softmax_cascade_kernel<<<batch, NT>>>(x, out);
}

// round 10
// speedup vs baseline: 1.3218x; 1.3218x over previous
#include <cuda_runtime.h>
#include <cuda_bf16.h>

// Tree: BRANCH=8, DEPTH=4. Level sizes 1,8,64,512,4096; offsets 0,1,9,73,585,4681.
// parent(c) = (c-1)>>3 for all c >= 1.
#define E_TOTAL   4681
#define NT        512
#define GRID_P    592      // 148 SMs x 4 CTAs resident

__global__ __launch_bounds__(NT, 4)
void softmax_cascade_kernel(const float* __restrict__ x,
                            float* __restrict__ out,
                            int batch)
{
    __shared__ float rs[585];    // per-group softmax ratio of internal nodes
    __shared__ float ps3[512];   // cumulative path prob of level-3 nodes (73+i)

    const int t      = threadIdx.x;
    const int stride = gridDim.x;

    int row = blockIdx.x;

    // ---- prologue: issue first row's loads (10 independent LDGs) ---------
    const float* __restrict__ xr0 = x + (size_t)row * E_TOTAL;
    float xa = xr0[1 + t];                               // nodes 1..512
    float xb = (t < 72) ? xr0[513 + t] : 0.0f;           // nodes 513..584
    float lx[8];                                         // leaves
#pragma unroll
    for (int i = 0; i < 8; ++i)
        lx[i] = xr0[585 + i * NT + t];

    while (true) {
        float* __restrict__ outr = out + (size_t)row * E_TOTAL;
        const int  nrow = row + stride;
        const bool more = (nrow < batch);
        // Clamped pointer: only dereferenced when 'more' is true.
        const float* __restrict__ nxr =
            x + (size_t)(more ? nrow : row) * E_TOTAL;

        // ------- Phase A: per-group softmax ratios (all internal levels) --
        // Thread t handles node c = 1+t; 8-child groups are 8-aligned in t.
        {
            float e = __expf(xa);
            float g = e;
            g += __shfl_xor_sync(0xffffffffu, g, 1);
            g += __shfl_xor_sync(0xffffffffu, g, 2);
            g += __shfl_xor_sync(0xffffffffu, g, 4);
            rs[1 + t] = __fdividef(e, g);
        }
        if (t < 128) {  // warps 0-3 fully active; lanes t>=72 compute garbage, discarded
            float e = __expf(xb);
            float g = e;
            g += __shfl_xor_sync(0xffffffffu, g, 1);
            g += __shfl_xor_sync(0xffffffffu, g, 2);
            g += __shfl_xor_sync(0xffffffffu, g, 4);
            if (t < 72) rs[513 + t] = __fdividef(e, g);
        }
        // prefetch next row's internal-node values (registers now free)
        if (more) {
            xa = nxr[1 + t];
            xb = (t < 72) ? nxr[513 + t] : 0.0f;
        }
        __syncthreads();

        // ------- Phase B: path products (depth <= 3, no chaining) ---------
        {
            const int c  = 73 + t;          // level-3 node
            const int p2 = (c - 1) >> 3;    // level-2 parent
            const int p1 = (p2 - 1) >> 3;   // level-1 ancestor
            const float p = rs[c] * rs[p2] * rs[p1];
            ps3[t]  = p;
            outr[c] = p;
        }
        if (t < 73) {
            if (t == 72) {
                outr[0] = 1.0f;             // root
            } else {
                const int c = 1 + t;        // levels 1..2
                float p = rs[c];
                if (c >= 9) p *= rs[(c - 1) >> 3];
                outr[c] = p;
            }
        }
        __syncthreads();

        // ------- Leaves: consume lx[i], immediately refill for next row ---
#pragma unroll
        for (int i = 0; i < 8; ++i) {
            const int idx = i * NT + t;     // 0..4095
            float e = __expf(lx[i]);
            float g = e;
            g += __shfl_xor_sync(0xffffffffu, g, 1);
            g += __shfl_xor_sync(0xffffffffu, g, 2);
            g += __shfl_xor_sync(0xffffffffu, g, 4);
            outr[585 + idx] = __fdividef(e, g) * ps3[idx >> 3];
            if (more) lx[i] = nxr[585 + idx];   // next-row prefetch, reg reuse
        }

        if (!more) break;
        row = nrow;
        __syncthreads();   // protect rs/ps3 reuse across iterations
    }
}

extern "C" void kernel_launch(void* const* d_in, const int* in_sizes, int n_in,
                              void* d_out, int out_size)
{
    const float* x = (const float*)d_in[0];   // inputs [B, E] fp32
    float* out = (float*)d_out;
    const int batch = in_sizes[0] / E_TOTAL;  // 8192
    const int grid  = batch < GRID_P ? batch : GRID_P;
    softmax_cascade_kernel<<<grid, NT>>>(x, out, batch);
}